// round 16
// baseline (speedup 1.0000x reference)
#include <cuda_runtime.h>
#include <cuda_bf16.h>
#include <cstdint>

#define NN 50000
#define NE 800000

// Scratch (device globals: no allocation allowed)
__device__ float g_h[NN * 64];
__device__ float g_A[NN * 64];
__device__ float g_B[NN * 64];
__device__ float g_agg[NN * 64];
__device__ float g_deg[NN];
__device__ int   g_is64;
// Per-layer w1 transposed + bf16-split, padded: hi[64 rows][36 words] then lo.
__device__ uint32_t g_w1t[4 * 4608];

// Packed fp32x2 FMA
__device__ __forceinline__ void ffma2(unsigned long long& d,
                                      unsigned long long a,
                                      unsigned long long b) {
    asm("fma.rn.f32x2 %0, %1, %2, %0;" : "+l"(d) : "l"(a), "l"(b));
}

// ---------------------------------------------------------------------------
// Edge-index dtype handling
// ---------------------------------------------------------------------------
__device__ __forceinline__ void load_edge(const void* ei, int e, int& src, int& dst) {
    if (g_is64) {
        const long long* p = (const long long*)ei;
        src = (int)p[e];
        dst = (int)p[NE + e];
    } else {
        const int* p = (const int*)ei;
        src = p[e];
        dst = p[NE + e];
    }
}

// ---------------------------------------------------------------------------
// prep_kernel: block 0 detects edge dtype; blocks 1..4 build w1T hi/lo
// ---------------------------------------------------------------------------
__global__ void prep_kernel(const int* __restrict__ ei32,
                            const float* __restrict__ w1all) {
    __shared__ int any;
    if (blockIdx.x == 0) {
        if (threadIdx.x == 0) any = 0;
        __syncthreads();
        for (int i = threadIdx.x; i < 4096; i += 256)
            if (ei32[2 * i + 1] != 0) any = 1;
        __syncthreads();
        if (threadIdx.x == 0) g_is64 = (any == 0) ? 1 : 0;
    } else {
        int layer = blockIdx.x - 1;
        const float* w1 = w1all + layer * 4096;
        __nv_bfloat16* gw = (__nv_bfloat16*)(g_w1t + layer * 4608);
        for (int i = threadIdx.x; i < 4096; i += 256) {
            int k = i >> 6, j = i & 63;
            float w = w1[i];
            __nv_bfloat16 h = __float2bfloat16(w);
            __nv_bfloat16 l = __float2bfloat16(w - __bfloat162float(h));
            gw[j * 72 + k] = h;
            gw[4608 + j * 72 + k] = l;
        }
    }
}

// ---------------------------------------------------------------------------
// h = x @ lin_in_w + lin_in_b   ([50000,16] @ [16,64])
// ---------------------------------------------------------------------------
__global__ void lin_in_kernel(const float* __restrict__ x,
                              const float* __restrict__ w,
                              const float* __restrict__ b) {
    __shared__ float ws[16 * 64];
    __shared__ float bs[64];
    __shared__ float xs[4][16];
    int tid = threadIdx.x;
    for (int i = tid; i < 16 * 64; i += 256) ws[i] = w[i];
    if (tid < 64) bs[tid] = b[tid];
    if (tid < 64) {
        int nl = tid >> 4, c = tid & 15;
        int n = blockIdx.x * 4 + nl;
        xs[nl][c] = x[n * 16 + c];
    }
    __syncthreads();
    int j = tid & 63, nl = tid >> 6;
    int n = blockIdx.x * 4 + nl;
    float acc = bs[j];
#pragma unroll
    for (int c = 0; c < 16; c++) acc = fmaf(xs[nl][c], ws[c * 64 + j], acc);
    g_h[n * 64 + j] = acc;
}

__global__ void zero_deg_kernel() {
    int i = blockIdx.x * 256 + threadIdx.x;
    if (i < NN) g_deg[i] = 0.0f;
}

__global__ void count_deg_kernel(const void* __restrict__ ei) {
    int e = blockIdx.x * 256 + threadIdx.x;
    int src, dst;
    load_edge(ei, e, src, dst);
    atomicAdd(&g_deg[dst], 1.0f);
}

// ---------------------------------------------------------------------------
// AB GEMM inner (f32x2, j-pair layout): thread (jp, grp) handles 2 nodes x
// j-pair; 16 MACs per c-step as 4 FFMA2.
// ---------------------------------------------------------------------------
__device__ __forceinline__ void gemm_AB_store(const float* w0s,
                                              const float (*hsx)[64],
                                              int n0, int jp, int grp) {
    int l0 = grp * 2, l1 = grp * 2 + 1;
    unsigned long long aA0 = 0, aA1 = 0, aB0 = 0, aB1 = 0;
#pragma unroll 8
    for (int c = 0; c < 64; c++) {
        unsigned long long wa2 = *(const unsigned long long*)(w0s + c * 64 + jp * 2);
        unsigned long long wb2 = *(const unsigned long long*)(w0s + (64 + c) * 64 + jp * 2);
        float h0 = hsx[l0][c], h1 = hsx[l1][c];
        unsigned long long h02, h12;
        asm("mov.b64 %0, {%1, %1};" : "=l"(h02) : "f"(h0));
        asm("mov.b64 %0, {%1, %1};" : "=l"(h12) : "f"(h1));
        ffma2(aA0, h02, wa2);
        ffma2(aA1, h12, wa2);
        ffma2(aB0, h02, wb2);
        ffma2(aB1, h12, wb2);
    }
    *(unsigned long long*)(g_A + (n0 + l0) * 64 + jp * 2) = aA0;
    *(unsigned long long*)(g_A + (n0 + l1) * 64 + jp * 2) = aA1;
    *(unsigned long long*)(g_B + (n0 + l0) * 64 + jp * 2) = aB0;
    *(unsigned long long*)(g_B + (n0 + l1) * 64 + jp * 2) = aB1;
}

// ---------------------------------------------------------------------------
// nodeAB (layer 0 only): A/B = g_h @ w0, zero g_agg rows.
// ---------------------------------------------------------------------------
__global__ __launch_bounds__(256) void nodeAB_kernel(const float* __restrict__ w0k) {
    __shared__ float w0s[128 * 64];
    __shared__ float hs[16][64];
    int tid = threadIdx.x;
    for (int i = tid; i < 128 * 64; i += 256) w0s[i] = w0k[i];
    int n0 = blockIdx.x * 16;
    for (int i = tid; i < 1024; i += 256)
        hs[i >> 6][i & 63] = g_h[(n0 + (i >> 6)) * 64 + (i & 63)];
    ((float4*)(g_agg + n0 * 64))[tid] = make_float4(0.f, 0.f, 0.f, 0.f);
    __syncthreads();
    gemm_AB_store(w0s, hs, n0, tid & 31, tid >> 5);
}

// ---------------------------------------------------------------------------
// fused_node: h = g_agg @ w2prev + deg*b2prev  (in SMEM), then
//             A/B = h @ w0next ; also zeroes g_agg rows.
// Dynamic SMEM: w2s 16K | w0s 32K | hs 4K | bs 256 | degs 64 = 53568 B
// ---------------------------------------------------------------------------
#define FN_SMEM 53568

__global__ __launch_bounds__(256) void fused_node_kernel(const float* __restrict__ w2p,
                                                         const float* __restrict__ b2p,
                                                         const float* __restrict__ w0n) {
    extern __shared__ float fsm[];
    float* w2s = fsm;                                    // 4096
    float* w0s = fsm + 4096;                             // 8192
    float (*hs)[64] = (float(*)[64])(fsm + 12288);       // 1024
    float* bs = fsm + 13312;                             // 64
    float* degs = fsm + 13376;                           // 16
    int tid = threadIdx.x;
    int n0 = blockIdx.x * 16;
    for (int i = tid; i < 4096; i += 256) w2s[i] = w2p[i];
    for (int i = tid; i < 8192; i += 256) w0s[i] = w0n[i];
    for (int i = tid; i < 1024; i += 256)
        hs[i >> 6][i & 63] = g_agg[(n0 + (i >> 6)) * 64 + (i & 63)];
    if (tid < 64) bs[tid] = b2p[tid];
    if (tid < 16) degs[tid] = g_deg[n0 + tid];
    __syncthreads();
    // zero agg rows for the next edge layer (hs already holds the values)
    ((float4*)(g_agg + n0 * 64))[tid] = make_float4(0.f, 0.f, 0.f, 0.f);

    int jp = tid & 31, grp = tid >> 5;
    int l0 = grp * 2, l1 = grp * 2 + 1;

    // ---- h = agg @ w2 + deg * b2 (f32x2) ----
    float2 bp = *(const float2*)(bs + jp * 2);
    float d0 = degs[l0], d1 = degs[l1];
    float i00 = d0 * bp.x, i01 = d0 * bp.y;
    float i10 = d1 * bp.x, i11 = d1 * bp.y;
    unsigned long long acc0, acc1;
    asm("mov.b64 %0, {%1, %2};" : "=l"(acc0) : "f"(i00), "f"(i01));
    asm("mov.b64 %0, {%1, %2};" : "=l"(acc1) : "f"(i10), "f"(i11));
#pragma unroll 8
    for (int c = 0; c < 64; c++) {
        unsigned long long wv2 = *(const unsigned long long*)(w2s + c * 64 + jp * 2);
        float h0 = hs[l0][c], h1 = hs[l1][c];
        unsigned long long h02, h12;
        asm("mov.b64 %0, {%1, %1};" : "=l"(h02) : "f"(h0));
        asm("mov.b64 %0, {%1, %1};" : "=l"(h12) : "f"(h1));
        ffma2(acc0, h02, wv2);
        ffma2(acc1, h12, wv2);
    }
    __syncthreads();  // all hs reads done before overwrite
    *(unsigned long long*)(&hs[l0][jp * 2]) = acc0;
    *(unsigned long long*)(&hs[l1][jp * 2]) = acc1;
    __syncthreads();

    // ---- A/B = h @ w0next ----
    gemm_AB_store(w0s, hs, n0, jp, grp);
}

// ---------------------------------------------------------------------------
// fused_out: h = g_agg @ w2[3] + deg*b2[3], then out = h @ lin_out_w + lin_out_b
// ---------------------------------------------------------------------------
__global__ __launch_bounds__(256) void fused_out_kernel(const float* __restrict__ w2p,
                                                        const float* __restrict__ b2p,
                                                        const float* __restrict__ low,
                                                        const float* __restrict__ lob,
                                                        float* __restrict__ out) {
    __shared__ float w2s[4096];
    __shared__ float hs[16][64];
    __shared__ float lows[64 * 16];
    __shared__ float bs[64];
    __shared__ float lobs[16];
    __shared__ float degs[16];
    int tid = threadIdx.x;
    int n0 = blockIdx.x * 16;
    for (int i = tid; i < 4096; i += 256) w2s[i] = w2p[i];
    for (int i = tid; i < 1024; i += 256) lows[i] = low[i];
    for (int i = tid; i < 1024; i += 256)
        hs[i >> 6][i & 63] = g_agg[(n0 + (i >> 6)) * 64 + (i & 63)];
    if (tid < 64) bs[tid] = b2p[tid];
    if (tid < 16) { lobs[tid] = lob[tid]; degs[tid] = g_deg[n0 + tid]; }
    __syncthreads();

    int jp = tid & 31, grp = tid >> 5;
    int l0 = grp * 2, l1 = grp * 2 + 1;
    float2 bp = *(const float2*)(bs + jp * 2);
    float d0 = degs[l0], d1 = degs[l1];
    float i00 = d0 * bp.x, i01 = d0 * bp.y;
    float i10 = d1 * bp.x, i11 = d1 * bp.y;
    unsigned long long acc0, acc1;
    asm("mov.b64 %0, {%1, %2};" : "=l"(acc0) : "f"(i00), "f"(i01));
    asm("mov.b64 %0, {%1, %2};" : "=l"(acc1) : "f"(i10), "f"(i11));
#pragma unroll 8
    for (int c = 0; c < 64; c++) {
        unsigned long long wv2 = *(const unsigned long long*)(w2s + c * 64 + jp * 2);
        float h0 = hs[l0][c], h1 = hs[l1][c];
        unsigned long long h02, h12;
        asm("mov.b64 %0, {%1, %1};" : "=l"(h02) : "f"(h0));
        asm("mov.b64 %0, {%1, %1};" : "=l"(h12) : "f"(h1));
        ffma2(acc0, h02, wv2);
        ffma2(acc1, h12, wv2);
    }
    __syncthreads();
    *(unsigned long long*)(&hs[l0][jp * 2]) = acc0;
    *(unsigned long long*)(&hs[l1][jp * 2]) = acc1;
    __syncthreads();

    // out = h @ lin_out_w + lin_out_b  (16 cols)
    int j = tid & 15, nl = tid >> 4;
    float acc = lobs[j];
#pragma unroll 16
    for (int c = 0; c < 64; c++)
        acc = fmaf(hs[nl][c], lows[c * 16 + j], acc);
    out[(n0 + nl) * 16 + j] = acc;
}

// ---------------------------------------------------------------------------
// HMMA helper: mma.sync.m16n8k16 row.col f32.bf16.bf16.f32
// ---------------------------------------------------------------------------
__device__ __forceinline__ void mma16816(float* c, const uint32_t* a, const uint32_t* b) {
    asm volatile(
        "mma.sync.aligned.m16n8k16.row.col.f32.bf16.bf16.f32 "
        "{%0,%1,%2,%3}, {%4,%5,%6,%7}, {%8,%9}, {%0,%1,%2,%3};"
        : "+f"(c[0]), "+f"(c[1]), "+f"(c[2]), "+f"(c[3])
        : "r"(a[0]), "r"(a[1]), "r"(a[2]), "r"(a[3]), "r"(b[0]), "r"(b[1]));
}

// ---------------------------------------------------------------------------
// Edge MMA kernel (UNCHANGED from R14 — proven at 141.6 us).
// ---------------------------------------------------------------------------
#define EMM_SMEM 55808

__global__ __launch_bounds__(128) void edge_mma_kernel(const void* __restrict__ ei,
                                                       int layer,
                                                       const float* __restrict__ b0,
                                                       const float* __restrict__ b1) {
    extern __shared__ char smem[];
    float* b0s = (float*)smem;
    float* b1s = (float*)(smem + 256);
    uint32_t* W1 = (uint32_t*)(smem + 512);
    int tid = threadIdx.x, warp = tid >> 5, lane = tid & 31;
    uint32_t* W = (uint32_t*)(smem + 18944) + warp * 2304;

    if (tid < 64) { b0s[tid] = b0[tid]; b1s[tid] = b1[tid]; }
    {
        const uint4* src = (const uint4*)(g_w1t + layer * 4608);
        uint4* dst = (uint4*)W1;
        for (int i = tid; i < 1152; i += 128) dst[i] = src[i];
    }
    __syncthreads();

    int e_tile = blockIdx.x * 128 + warp * 32;
    int ln4 = lane >> 2, q = lane & 3;

#pragma unroll 1
    for (int p = 0; p < 4; p++) {
        int el = p * 8 + ln4;
        int s_, d_;
        load_edge(ei, e_tile + el, s_, d_);
        const float4* Ar = (const float4*)(g_A + s_ * 64) + q;
        const float4* Br = (const float4*)(g_B + d_ * 64) + q;
#pragma unroll
        for (int i = 0; i < 4; i++) {
            float4 a = __ldg(Ar + i * 4);
            float4 b = __ldg(Br + i * 4);
            float4 c = ((const float4*)b0s)[i * 4 + q];
            float v0 = fmaxf(a.x + b.x + c.x, 0.f);
            float v1 = fmaxf(a.y + b.y + c.y, 0.f);
            float v2 = fmaxf(a.z + b.z + c.z, 0.f);
            float v3 = fmaxf(a.w + b.w + c.w, 0.f);
            __nv_bfloat16 h0 = __float2bfloat16(v0), h1 = __float2bfloat16(v1);
            __nv_bfloat16 h2 = __float2bfloat16(v2), h3 = __float2bfloat16(v3);
            __nv_bfloat16 l0 = __float2bfloat16(v0 - __bfloat162float(h0));
            __nv_bfloat16 l1 = __float2bfloat16(v1 - __bfloat162float(h1));
            __nv_bfloat16 l2 = __float2bfloat16(v2 - __bfloat162float(h2));
            __nv_bfloat16 l3 = __float2bfloat16(v3 - __bfloat162float(h3));
            uint32_t hw0 = (uint32_t)__bfloat16_as_ushort(h0) |
                           ((uint32_t)__bfloat16_as_ushort(h1) << 16);
            uint32_t hw1 = (uint32_t)__bfloat16_as_ushort(h2) |
                           ((uint32_t)__bfloat16_as_ushort(h3) << 16);
            uint32_t lw0 = (uint32_t)__bfloat16_as_ushort(l0) |
                           ((uint32_t)__bfloat16_as_ushort(l1) << 16);
            uint32_t lw1 = (uint32_t)__bfloat16_as_ushort(l2) |
                           ((uint32_t)__bfloat16_as_ushort(l3) << 16);
            uint32_t base = (uint32_t)(el * 36 + i * 8 + q * 2);
            *(uint2*)(W + base)        = make_uint2(hw0, hw1);
            *(uint2*)(W + 1152 + base) = make_uint2(lw0, lw1);
        }
    }
    __syncwarp();

    uint32_t Af[2][2][4][4];
#pragma unroll
    for (int mt = 0; mt < 2; mt++)
#pragma unroll
        for (int v = 0; v < 2; v++)
#pragma unroll
            for (int kt = 0; kt < 4; kt++) {
                int r0 = mt * 16 + ln4;
                int w0i = v * 1152 + r0 * 36 + kt * 8 + q;
                int w1i = v * 1152 + (r0 + 8) * 36 + kt * 8 + q;
                Af[mt][v][kt][0] = W[w0i];
                Af[mt][v][kt][1] = W[w1i];
                Af[mt][v][kt][2] = W[w0i + 4];
                Af[mt][v][kt][3] = W[w1i + 4];
            }
    __syncwarp();

    float* ep = (float*)W;
#pragma unroll 1
    for (int nt = 0; nt < 8; nt++) {
        uint32_t Bh[4][2], Bl[4][2];
        int nrow = nt * 8 + ln4;
#pragma unroll
        for (int kt = 0; kt < 4; kt++) {
            int wi = nrow * 36 + kt * 8 + q;
            Bh[kt][0] = W1[wi];        Bh[kt][1] = W1[wi + 4];
            Bl[kt][0] = W1[2304 + wi]; Bl[kt][1] = W1[2304 + wi + 4];
        }
        int col = nt * 8 + q * 2;
        float bias0 = b1s[col], bias1 = b1s[col + 1];
        float C[2][4];
#pragma unroll
        for (int mt = 0; mt < 2; mt++) {
            C[mt][0] = bias0; C[mt][1] = bias1; C[mt][2] = bias0; C[mt][3] = bias1;
        }
#pragma unroll
        for (int kt = 0; kt < 4; kt++)
#pragma unroll
            for (int mt = 0; mt < 2; mt++) {
                mma16816(C[mt], Af[mt][0][kt], Bh[kt]);
                mma16816(C[mt], Af[mt][0][kt], Bl[kt]);
                mma16816(C[mt], Af[mt][1][kt], Bh[kt]);
            }
#pragma unroll
        for (int mt = 0; mt < 2; mt++) {
            int r = mt * 16 + ln4;
            float2 v01 = make_float2(fmaxf(C[mt][0], 0.f), fmaxf(C[mt][1], 0.f));
            float2 v23 = make_float2(fmaxf(C[mt][2], 0.f), fmaxf(C[mt][3], 0.f));
            *(float2*)(ep + r * 72 + nt * 8 + q * 2)       = v01;
            *(float2*)(ep + (r + 8) * 72 + nt * 8 + q * 2) = v23;
        }
    }
    __syncwarp();

#pragma unroll 1
    for (int p = 0; p < 4; p++) {
        int el = p * 8 + ln4;
        int s_, d_;
        load_edge(ei, e_tile + el, s_, d_);
        float* outp = g_agg + d_ * 64;
#pragma unroll
        for (int i = 0; i < 4; i++) {
            float4 v = *(const float4*)(ep + el * 72 + i * 16 + q * 4);
            asm volatile("red.global.add.v4.f32 [%0], {%1, %2, %3, %4};"
                         :: "l"(outp + i * 16 + q * 4),
                            "f"(v.x), "f"(v.y), "f"(v.z), "f"(v.w)
                         : "memory");
        }
    }
}

// ---------------------------------------------------------------------------
// Launch.  edge_mma_kernel at launch #4 (profiled slot); count_deg before
// the first fused_node (which consumes g_deg).
// ---------------------------------------------------------------------------
extern "C" void kernel_launch(void* const* d_in, const int* in_sizes, int n_in,
                              void* d_out, int out_size) {
    const float* x        = (const float*)d_in[0];
    // d_in[1] = lframes (unused by the reference)
    const void*  ei       = d_in[2];
    const float* lin_in_w = (const float*)d_in[3];
    const float* lin_in_b = (const float*)d_in[4];
    const float* w0       = (const float*)d_in[5];
    const float* b0       = (const float*)d_in[6];
    const float* w1       = (const float*)d_in[7];
    const float* b1       = (const float*)d_in[8];
    const float* w2       = (const float*)d_in[9];
    const float* b2       = (const float*)d_in[10];
    const float* low      = (const float*)d_in[11];
    const float* lob      = (const float*)d_in[12];
    float* out = (float*)d_out;

    cudaFuncSetAttribute(edge_mma_kernel,
                         cudaFuncAttributeMaxDynamicSharedMemorySize, EMM_SMEM);
    cudaFuncSetAttribute(fused_node_kernel,
                         cudaFuncAttributeMaxDynamicSharedMemorySize, FN_SMEM);

    prep_kernel<<<5, 256>>>((const int*)ei, w1);                         // 1
    lin_in_kernel<<<NN / 4, 256>>>(x, lin_in_w, lin_in_b);               // 2
    nodeAB_kernel<<<NN / 16, 256>>>(w0);                                 // 3
    edge_mma_kernel<<<NE / 128, 128, EMM_SMEM>>>(ei, 0, b0, b1);         // 4 <- profile
    zero_deg_kernel<<<(NN + 255) / 256, 256>>>();                        // 5
    count_deg_kernel<<<NE / 256, 256>>>(ei);                             // 6

    for (int k = 1; k < 4; k++) {
        fused_node_kernel<<<NN / 16, 256, FN_SMEM>>>(w2 + (k - 1) * 4096,
                                                     b2 + (k - 1) * 64,
                                                     w0 + k * 8192);
        edge_mma_kernel<<<NE / 128, 128, EMM_SMEM>>>(ei, k, b0 + k * 64, b1 + k * 64);
    }

    fused_out_kernel<<<NN / 16, 256>>>(w2 + 3 * 4096, b2 + 3 * 64, low, lob, out);
}

// round 17
// speedup vs baseline: 1.0550x; 1.0550x over previous
#include <cuda_runtime.h>
#include <cuda_bf16.h>
#include <cstdint>

#define NN 50000
#define NE 800000

// Scratch (device globals: no allocation allowed)
__device__ float g_h[NN * 64];
__device__ float g_A[NN * 64];
__device__ float g_B[NN * 64];
__device__ float g_agg[NN * 64];
__device__ float g_deg[NN];
__device__ int   g_is64;
// Per-layer w1 transposed + bf16-split, padded: hi[64 rows][36 words] then lo.
__device__ uint32_t g_w1t[4 * 4608];

// ---------------------------------------------------------------------------
// Edge-index dtype handling
// ---------------------------------------------------------------------------
__device__ __forceinline__ void load_edge(const void* ei, int e, int& src, int& dst) {
    if (g_is64) {
        const long long* p = (const long long*)ei;
        src = (int)p[e];
        dst = (int)p[NE + e];
    } else {
        const int* p = (const int*)ei;
        src = p[e];
        dst = p[NE + e];
    }
}

// ---------------------------------------------------------------------------
// prep_kernel: block 0 detects edge dtype; blocks 1..4 build w1T hi/lo
// ---------------------------------------------------------------------------
__global__ void prep_kernel(const int* __restrict__ ei32,
                            const float* __restrict__ w1all) {
    __shared__ int any;
    if (blockIdx.x == 0) {
        if (threadIdx.x == 0) any = 0;
        __syncthreads();
        for (int i = threadIdx.x; i < 4096; i += 256)
            if (ei32[2 * i + 1] != 0) any = 1;
        __syncthreads();
        if (threadIdx.x == 0) g_is64 = (any == 0) ? 1 : 0;
    } else {
        int layer = blockIdx.x - 1;
        const float* w1 = w1all + layer * 4096;
        __nv_bfloat16* gw = (__nv_bfloat16*)(g_w1t + layer * 4608);
        for (int i = threadIdx.x; i < 4096; i += 256) {
            int k = i >> 6, j = i & 63;
            float w = w1[i];
            __nv_bfloat16 h = __float2bfloat16(w);
            __nv_bfloat16 l = __float2bfloat16(w - __bfloat162float(h));
            gw[j * 72 + k] = h;
            gw[4608 + j * 72 + k] = l;
        }
    }
}

// ---------------------------------------------------------------------------
// h = x @ lin_in_w + lin_in_b   ([50000,16] @ [16,64])
// ---------------------------------------------------------------------------
__global__ void lin_in_kernel(const float* __restrict__ x,
                              const float* __restrict__ w,
                              const float* __restrict__ b) {
    __shared__ float ws[16 * 64];
    __shared__ float bs[64];
    __shared__ float xs[4][16];
    int tid = threadIdx.x;
    for (int i = tid; i < 16 * 64; i += 256) ws[i] = w[i];
    if (tid < 64) bs[tid] = b[tid];
    if (tid < 64) {
        int nl = tid >> 4, c = tid & 15;
        int n = blockIdx.x * 4 + nl;
        xs[nl][c] = x[n * 16 + c];
    }
    __syncthreads();
    int j = tid & 63, nl = tid >> 6;
    int n = blockIdx.x * 4 + nl;
    float acc = bs[j];
#pragma unroll
    for (int c = 0; c < 16; c++) acc = fmaf(xs[nl][c], ws[c * 64 + j], acc);
    g_h[n * 64 + j] = acc;
}

__global__ void zero_deg_kernel() {
    int i = blockIdx.x * 256 + threadIdx.x;
    if (i < NN) g_deg[i] = 0.0f;
}

__global__ void count_deg_kernel(const void* __restrict__ ei) {
    int e = blockIdx.x * 256 + threadIdx.x;
    int src, dst;
    load_edge(ei, e, src, dst);
    atomicAdd(&g_deg[dst], 1.0f);
}

// ---------------------------------------------------------------------------
// A = h @ w0[0:64,:],  B = h @ w0[64:128,:].  Also zeroes g_agg rows.
// (R14 version — proven.)
// ---------------------------------------------------------------------------
__global__ __launch_bounds__(256) void nodeAB_kernel(const float* __restrict__ w0k) {
    __shared__ float w0s[128 * 64];
    __shared__ float hs[16][64];
    int tid = threadIdx.x;
    for (int i = tid; i < 128 * 64; i += 256) w0s[i] = w0k[i];
    int n0 = blockIdx.x * 16;
    for (int i = tid; i < 16 * 64; i += 256)
        hs[i >> 6][i & 63] = g_h[(n0 + (i >> 6)) * 64 + (i & 63)];
    {
        float4 z = make_float4(0.f, 0.f, 0.f, 0.f);
        ((float4*)(g_agg + n0 * 64))[tid] = z;
    }
    __syncthreads();
    int j = tid & 63, grp = tid >> 6;
    float a[4] = {0, 0, 0, 0}, bb[4] = {0, 0, 0, 0};
#pragma unroll 8
    for (int c = 0; c < 64; c++) {
        float wa = w0s[c * 64 + j];
        float wb = w0s[(64 + c) * 64 + j];
#pragma unroll
        for (int i = 0; i < 4; i++) {
            float hv = hs[grp * 4 + i][c];
            a[i]  = fmaf(hv, wa, a[i]);
            bb[i] = fmaf(hv, wb, bb[i]);
        }
    }
#pragma unroll
    for (int i = 0; i < 4; i++) {
        int n = n0 + grp * 4 + i;
        g_A[n * 64 + j] = a[i];
        g_B[n * 64 + j] = bb[i];
    }
}

// ---------------------------------------------------------------------------
// HMMA helper: mma.sync.m16n8k16 row.col f32.bf16.bf16.f32
// ---------------------------------------------------------------------------
__device__ __forceinline__ void mma16816(float* c, const uint32_t* a, const uint32_t* b) {
    asm volatile(
        "mma.sync.aligned.m16n8k16.row.col.f32.bf16.bf16.f32 "
        "{%0,%1,%2,%3}, {%4,%5,%6,%7}, {%8,%9}, {%0,%1,%2,%3};"
        : "+f"(c[0]), "+f"(c[1]), "+f"(c[2]), "+f"(c[3])
        : "r"(a[0]), "r"(a[1]), "r"(a[2]), "r"(a[3]), "r"(b[0]), "r"(b[1]));
}

// ---------------------------------------------------------------------------
// Edge MMA kernel.  R14 structure; ONE change: B (w1) fragments are read
// directly from g_w1t via __ldg (18KB stays hot in L1) instead of a per-CTA
// SMEM copy.  SMEM drops 55.8KB -> 37.4KB => 6 CTAs/SM = 24 warps (+50%).
// SMEM: b0s 256 | b1s 256 | 4 x warp stage 9216 = 37376
// ---------------------------------------------------------------------------
#define EMM_SMEM 37376

__global__ __launch_bounds__(128) void edge_mma_kernel(const void* __restrict__ ei,
                                                       int layer,
                                                       const float* __restrict__ b0,
                                                       const float* __restrict__ b1) {
    extern __shared__ char smem[];
    float* b0s = (float*)smem;
    float* b1s = (float*)(smem + 256);
    int tid = threadIdx.x, warp = tid >> 5, lane = tid & 31;
    uint32_t* W = (uint32_t*)(smem + 512) + warp * 2304;
    const uint32_t* __restrict__ W1g = g_w1t + layer * 4608;

    if (tid < 64) { b0s[tid] = b0[tid]; b1s[tid] = b1[tid]; }
    __syncthreads();

    int e_tile = blockIdx.x * 128 + warp * 32;
    int ln4 = lane >> 2, q = lane & 3;

    // ---- gather + relu + bf16 split into stage (4 passes x 8 edges) ----
#pragma unroll 1
    for (int p = 0; p < 4; p++) {
        int el = p * 8 + ln4;
        int s_, d_;
        load_edge(ei, e_tile + el, s_, d_);
        const float4* Ar = (const float4*)(g_A + s_ * 64) + q;
        const float4* Br = (const float4*)(g_B + d_ * 64) + q;
#pragma unroll
        for (int i = 0; i < 4; i++) {
            float4 a = __ldg(Ar + i * 4);
            float4 b = __ldg(Br + i * 4);
            float4 c = ((const float4*)b0s)[i * 4 + q];
            float v0 = fmaxf(a.x + b.x + c.x, 0.f);
            float v1 = fmaxf(a.y + b.y + c.y, 0.f);
            float v2 = fmaxf(a.z + b.z + c.z, 0.f);
            float v3 = fmaxf(a.w + b.w + c.w, 0.f);
            __nv_bfloat16 h0 = __float2bfloat16(v0), h1 = __float2bfloat16(v1);
            __nv_bfloat16 h2 = __float2bfloat16(v2), h3 = __float2bfloat16(v3);
            __nv_bfloat16 l0 = __float2bfloat16(v0 - __bfloat162float(h0));
            __nv_bfloat16 l1 = __float2bfloat16(v1 - __bfloat162float(h1));
            __nv_bfloat16 l2 = __float2bfloat16(v2 - __bfloat162float(h2));
            __nv_bfloat16 l3 = __float2bfloat16(v3 - __bfloat162float(h3));
            uint32_t hw0 = (uint32_t)__bfloat16_as_ushort(h0) |
                           ((uint32_t)__bfloat16_as_ushort(h1) << 16);
            uint32_t hw1 = (uint32_t)__bfloat16_as_ushort(h2) |
                           ((uint32_t)__bfloat16_as_ushort(h3) << 16);
            uint32_t lw0 = (uint32_t)__bfloat16_as_ushort(l0) |
                           ((uint32_t)__bfloat16_as_ushort(l1) << 16);
            uint32_t lw1 = (uint32_t)__bfloat16_as_ushort(l2) |
                           ((uint32_t)__bfloat16_as_ushort(l3) << 16);
            uint32_t base = (uint32_t)(el * 36 + i * 8 + q * 2);
            *(uint2*)(W + base)        = make_uint2(hw0, hw1);
            *(uint2*)(W + 1152 + base) = make_uint2(lw0, lw1);
        }
    }
    __syncwarp();

    // ---- load all A fragments into registers ----
    uint32_t Af[2][2][4][4];
#pragma unroll
    for (int mt = 0; mt < 2; mt++)
#pragma unroll
        for (int v = 0; v < 2; v++)
#pragma unroll
            for (int kt = 0; kt < 4; kt++) {
                int r0 = mt * 16 + ln4;
                int w0i = v * 1152 + r0 * 36 + kt * 8 + q;
                int w1i = v * 1152 + (r0 + 8) * 36 + kt * 8 + q;
                Af[mt][v][kt][0] = W[w0i];
                Af[mt][v][kt][1] = W[w1i];
                Af[mt][v][kt][2] = W[w0i + 4];
                Af[mt][v][kt][3] = W[w1i + 4];
            }
    __syncwarp();

    // ---- GEMM over 8 n-tiles; B fragments straight from global (L1-hot) ----
    float* ep = (float*)W;
#pragma unroll 1
    for (int nt = 0; nt < 8; nt++) {
        uint32_t Bh[4][2], Bl[4][2];
        int nrow = nt * 8 + ln4;
#pragma unroll
        for (int kt = 0; kt < 4; kt++) {
            int wi = nrow * 36 + kt * 8 + q;
            Bh[kt][0] = __ldg(W1g + wi);
            Bh[kt][1] = __ldg(W1g + wi + 4);
            Bl[kt][0] = __ldg(W1g + 2304 + wi);
            Bl[kt][1] = __ldg(W1g + 2304 + wi + 4);
        }
        int col = nt * 8 + q * 2;
        float bias0 = b1s[col], bias1 = b1s[col + 1];
        float C[2][4];
#pragma unroll
        for (int mt = 0; mt < 2; mt++) {
            C[mt][0] = bias0; C[mt][1] = bias1; C[mt][2] = bias0; C[mt][3] = bias1;
        }
#pragma unroll
        for (int kt = 0; kt < 4; kt++)
#pragma unroll
            for (int mt = 0; mt < 2; mt++) {
                mma16816(C[mt], Af[mt][0][kt], Bh[kt]);
                mma16816(C[mt], Af[mt][0][kt], Bl[kt]);
                mma16816(C[mt], Af[mt][1][kt], Bh[kt]);
            }
#pragma unroll
        for (int mt = 0; mt < 2; mt++) {
            int r = mt * 16 + ln4;
            float2 v01 = make_float2(fmaxf(C[mt][0], 0.f), fmaxf(C[mt][1], 0.f));
            float2 v23 = make_float2(fmaxf(C[mt][2], 0.f), fmaxf(C[mt][3], 0.f));
            *(float2*)(ep + r * 72 + nt * 8 + q * 2)       = v01;
            *(float2*)(ep + (r + 8) * 72 + nt * 8 + q * 2) = v23;
        }
    }
    __syncwarp();

    // ---- scatter: coalesced, red.global.add.v4 ----
#pragma unroll 1
    for (int p = 0; p < 4; p++) {
        int el = p * 8 + ln4;
        int s_, d_;
        load_edge(ei, e_tile + el, s_, d_);
        float* outp = g_agg + d_ * 64;
#pragma unroll
        for (int i = 0; i < 4; i++) {
            float4 v = *(const float4*)(ep + el * 72 + i * 16 + q * 4);
            asm volatile("red.global.add.v4.f32 [%0], {%1, %2, %3, %4};"
                         :: "l"(outp + i * 16 + q * 4),
                            "f"(v.x), "f"(v.y), "f"(v.z), "f"(v.w)
                         : "memory");
        }
    }
}

// ---------------------------------------------------------------------------
// h = agg @ w2 + deg * b2   ([50000,64] @ [64,64])   (R14 version)
// ---------------------------------------------------------------------------
__global__ __launch_bounds__(256) void nodeOut_kernel(const float* __restrict__ w2k,
                                                      const float* __restrict__ b2k) {
    __shared__ float ws[64 * 64];
    __shared__ float hs[16][64];
    __shared__ float bs[64];
    int tid = threadIdx.x;
    for (int i = tid; i < 64 * 64; i += 256) ws[i] = w2k[i];
    if (tid < 64) bs[tid] = b2k[tid];
    int n0 = blockIdx.x * 16;
    for (int i = tid; i < 16 * 64; i += 256)
        hs[i >> 6][i & 63] = g_agg[(n0 + (i >> 6)) * 64 + (i & 63)];
    __syncthreads();
    int j = tid & 63, grp = tid >> 6;
    float acc[4];
#pragma unroll
    for (int i = 0; i < 4; i++) acc[i] = g_deg[n0 + grp * 4 + i] * bs[j];
#pragma unroll 8
    for (int c = 0; c < 64; c++) {
        float wv = ws[c * 64 + j];
#pragma unroll
        for (int i = 0; i < 4; i++)
            acc[i] = fmaf(hs[grp * 4 + i][c], wv, acc[i]);
    }
#pragma unroll
    for (int i = 0; i < 4; i++)
        g_h[(n0 + grp * 4 + i) * 64 + j] = acc[i];
}

// ---------------------------------------------------------------------------
// out = h @ lin_out_w + lin_out_b   ([50000,64] @ [64,16])   (R14 version)
// ---------------------------------------------------------------------------
__global__ void lin_out_kernel(const float* __restrict__ w,
                               const float* __restrict__ b,
                               float* __restrict__ out) {
    __shared__ float ws[64 * 16];
    __shared__ float bs[16];
    __shared__ float hs[16][64];
    int tid = threadIdx.x;
    for (int i = tid; i < 64 * 16; i += 256) ws[i] = w[i];
    if (tid < 16) bs[tid] = b[tid];
    int n0 = blockIdx.x * 16;
    for (int i = tid; i < 16 * 64; i += 256)
        hs[i >> 6][i & 63] = g_h[(n0 + (i >> 6)) * 64 + (i & 63)];
    __syncthreads();
    int j = tid & 15, nl = tid >> 4;
    float acc = bs[j];
#pragma unroll 16
    for (int c = 0; c < 64; c++)
        acc = fmaf(hs[nl][c], ws[c * 16 + j], acc);
    out[(n0 + nl) * 16 + j] = acc;
}

// ---------------------------------------------------------------------------
// Launch (R14 schedule; edge_mma_kernel at launch #4 for the ncu capture).
// ---------------------------------------------------------------------------
extern "C" void kernel_launch(void* const* d_in, const int* in_sizes, int n_in,
                              void* d_out, int out_size) {
    const float* x        = (const float*)d_in[0];
    // d_in[1] = lframes (unused by the reference)
    const void*  ei       = d_in[2];
    const float* lin_in_w = (const float*)d_in[3];
    const float* lin_in_b = (const float*)d_in[4];
    const float* w0       = (const float*)d_in[5];
    const float* b0       = (const float*)d_in[6];
    const float* w1       = (const float*)d_in[7];
    const float* b1       = (const float*)d_in[8];
    const float* w2       = (const float*)d_in[9];
    const float* b2       = (const float*)d_in[10];
    const float* low      = (const float*)d_in[11];
    const float* lob      = (const float*)d_in[12];
    float* out = (float*)d_out;

    cudaFuncSetAttribute(edge_mma_kernel,
                         cudaFuncAttributeMaxDynamicSharedMemorySize, EMM_SMEM);

    prep_kernel<<<5, 256>>>((const int*)ei, w1);                        // 1
    lin_in_kernel<<<NN / 4, 256>>>(x, lin_in_w, lin_in_b);              // 2

    nodeAB_kernel<<<NN / 16, 256>>>(w0);                                // 3
    edge_mma_kernel<<<NE / 128, 128, EMM_SMEM>>>(ei, 0, b0, b1);        // 4 <- profile
    zero_deg_kernel<<<(NN + 255) / 256, 256>>>();                       // 5
    count_deg_kernel<<<NE / 256, 256>>>(ei);                            // 6
    nodeOut_kernel<<<NN / 16, 256>>>(w2, b2);                           // 7

    for (int k = 1; k < 4; k++) {
        nodeAB_kernel<<<NN / 16, 256>>>(w0 + k * 128 * 64);
        edge_mma_kernel<<<NE / 128, 128, EMM_SMEM>>>(ei, k, b0 + k * 64, b1 + k * 64);
        nodeOut_kernel<<<NN / 16, 256>>>(w2 + k * 64 * 64, b2 + k * 64);
    }

    lin_out_kernel<<<NN / 16, 256>>>(low, lob, out);
}